// round 1
// baseline (speedup 1.0000x reference)
#include <cuda_runtime.h>
#include <math.h>

// Problem constants (hard-coded in the reference module)
#define T_STEPS 30
#define ISZ     100
#define HSZ     256
#define NSEQ    5120          // 512 * 10
#define NBATCH  512

// State scratch (allocation-free rule: __device__ globals)
// h: ping-pong [parity][dir*NSEQ*HSZ + ...], c: [dir*NSEQ*HSZ + ...]
__device__ float g_h[2][2 * NSEQ * HSZ];
__device__ float g_c[2 * NSEQ * HSZ];

__global__ void init_state(const float* __restrict__ h0, const float* __restrict__ c0) {
    int i = blockIdx.x * blockDim.x + threadIdx.x;
    const int tot = 2 * NSEQ * HSZ;
    if (i < tot) {
        g_h[0][i] = h0[i];
        g_c[i]    = c0[i];
    }
}

__device__ __forceinline__ float sigm(float v) { return 1.0f / (1.0f + expf(-v)); }

// One LSTM timestep, both directions (blockIdx.z = dir).
// Each block: 64 batch rows x 64 hidden cols, computing ALL FOUR gate tiles
// (column offsets g*256) so the cell update is thread-local.
// GEMM K = 100 (input, from x) + 256 (hidden, from h_in), fp32.
__global__ __launch_bounds__(256) void lstm_step(
    const float* __restrict__ x,
    const float* __restrict__ Wih_f, const float* __restrict__ Whh_f,
    const float* __restrict__ bih_f, const float* __restrict__ bhh_f,
    const float* __restrict__ Wih_b, const float* __restrict__ Whh_b,
    const float* __restrict__ bih_b, const float* __restrict__ bhh_b,
    int s)
{
    const int d = blockIdx.z;
    const float* __restrict__ Wih = d ? Wih_b : Wih_f;
    const float* __restrict__ Whh = d ? Whh_b : Whh_f;
    const float* __restrict__ bih = d ? bih_b : bih_f;
    const float* __restrict__ bhh = d ? bhh_b : bhh_f;
    const int t = d ? (T_STEPS - 1 - s) : s;

    const float* __restrict__ h_in  = g_h[s & 1]       + d * (NSEQ * HSZ);
    float*       __restrict__ h_out = g_h[(s + 1) & 1] + d * (NSEQ * HSZ);
    float*       __restrict__ c_st  = g_c              + d * (NSEQ * HSZ);

    const int hbase = blockIdx.x * 64;   // hidden-col tile base (0..192)
    const int n0    = blockIdx.y * 64;   // batch-row tile base
    const int tid   = threadIdx.x;
    const int tx    = tid & 15;          // 16 col-threads (4 cols each)
    const int ty    = tid >> 4;          // 16 row-threads (4 rows each)

    __shared__ float As[64][17];         // [row][k], pad 17 -> conflict-free
    __shared__ float Bs[4][16][68];      // [gate][k][col], pad 68 (float4-aligned)

    float acc[4][4][4];                  // [gate][row][col]
#pragma unroll
    for (int g = 0; g < 4; g++)
#pragma unroll
        for (int r = 0; r < 4; r++)
#pragma unroll
            for (int c = 0; c < 4; c++) acc[g][r][c] = 0.0f;

    // ---------------- Phase 1: input contribution, K = 100 ----------------
    for (int kb = 0; kb < ISZ; kb += 16) {
        // load A tile: x[n, t, k]  (64 rows x 16 k)
#pragma unroll
        for (int j = 0; j < 4; j++) {
            int i   = tid + j * 256;
            int row = i >> 4;
            int k   = i & 15;
            int kg  = kb + k;
            As[row][k] = (kg < ISZ) ? x[(size_t)(n0 + row) * (T_STEPS * ISZ) + t * ISZ + kg] : 0.0f;
        }
        // load B tiles: Wih[(g*256 + hbase + col) * 100 + k] for 4 gates
#pragma unroll
        for (int j = 0; j < 16; j++) {
            int i   = tid + j * 256;
            int g   = i >> 10;
            int rem = i & 1023;
            int col = rem >> 4;
            int k   = rem & 15;
            int kg  = kb + k;
            Bs[g][k][col] = (kg < ISZ) ? Wih[(size_t)(g * HSZ + hbase + col) * ISZ + kg] : 0.0f;
        }
        __syncthreads();
#pragma unroll
        for (int k = 0; k < 16; k++) {
            float a0 = As[ty * 4 + 0][k];
            float a1 = As[ty * 4 + 1][k];
            float a2 = As[ty * 4 + 2][k];
            float a3 = As[ty * 4 + 3][k];
#pragma unroll
            for (int g = 0; g < 4; g++) {
                float4 b = *(const float4*)&Bs[g][k][tx * 4];
                acc[g][0][0] += a0 * b.x; acc[g][0][1] += a0 * b.y; acc[g][0][2] += a0 * b.z; acc[g][0][3] += a0 * b.w;
                acc[g][1][0] += a1 * b.x; acc[g][1][1] += a1 * b.y; acc[g][1][2] += a1 * b.z; acc[g][1][3] += a1 * b.w;
                acc[g][2][0] += a2 * b.x; acc[g][2][1] += a2 * b.y; acc[g][2][2] += a2 * b.z; acc[g][2][3] += a2 * b.w;
                acc[g][3][0] += a3 * b.x; acc[g][3][1] += a3 * b.y; acc[g][3][2] += a3 * b.z; acc[g][3][3] += a3 * b.w;
            }
        }
        __syncthreads();
    }

    // ---------------- Phase 2: hidden contribution, K = 256 ----------------
    for (int kb = 0; kb < HSZ; kb += 16) {
#pragma unroll
        for (int j = 0; j < 4; j++) {
            int i   = tid + j * 256;
            int row = i >> 4;
            int k   = i & 15;
            As[row][k] = h_in[(size_t)(n0 + row) * HSZ + kb + k];
        }
#pragma unroll
        for (int j = 0; j < 16; j++) {
            int i   = tid + j * 256;
            int g   = i >> 10;
            int rem = i & 1023;
            int col = rem >> 4;
            int k   = rem & 15;
            Bs[g][k][col] = Whh[(size_t)(g * HSZ + hbase + col) * HSZ + kb + k];
        }
        __syncthreads();
#pragma unroll
        for (int k = 0; k < 16; k++) {
            float a0 = As[ty * 4 + 0][k];
            float a1 = As[ty * 4 + 1][k];
            float a2 = As[ty * 4 + 2][k];
            float a3 = As[ty * 4 + 3][k];
#pragma unroll
            for (int g = 0; g < 4; g++) {
                float4 b = *(const float4*)&Bs[g][k][tx * 4];
                acc[g][0][0] += a0 * b.x; acc[g][0][1] += a0 * b.y; acc[g][0][2] += a0 * b.z; acc[g][0][3] += a0 * b.w;
                acc[g][1][0] += a1 * b.x; acc[g][1][1] += a1 * b.y; acc[g][1][2] += a1 * b.z; acc[g][1][3] += a1 * b.w;
                acc[g][2][0] += a2 * b.x; acc[g][2][1] += a2 * b.y; acc[g][2][2] += a2 * b.z; acc[g][2][3] += a2 * b.w;
                acc[g][3][0] += a3 * b.x; acc[g][3][1] += a3 * b.y; acc[g][3][2] += a3 * b.z; acc[g][3][3] += a3 * b.w;
            }
        }
        __syncthreads();
    }

    // ---------------- Epilogue: bias + LSTM cell, write h/c ----------------
#pragma unroll
    for (int c = 0; c < 4; c++) {
        const int col = hbase + tx * 4 + c;
        const float bi = bih[0 * HSZ + col] + bhh[0 * HSZ + col];
        const float bf = bih[1 * HSZ + col] + bhh[1 * HSZ + col];
        const float bg = bih[2 * HSZ + col] + bhh[2 * HSZ + col];
        const float bo = bih[3 * HSZ + col] + bhh[3 * HSZ + col];
#pragma unroll
        for (int r = 0; r < 4; r++) {
            const int n   = n0 + ty * 4 + r;
            const size_t idx = (size_t)n * HSZ + col;
            const float iv = sigm(acc[0][r][c] + bi);
            const float fv = sigm(acc[1][r][c] + bf);
            const float gv = tanhf(acc[2][r][c] + bg);
            const float ov = sigm(acc[3][r][c] + bo);
            const float cn = fv * c_st[idx] + iv * gv;
            c_st[idx]  = cn;
            h_out[idx] = ov * tanhf(cn);
        }
    }
}

// Head: x_fea assembly + Linear(2560->64) -> Linear(64->5) -> Softmax.
// One block per batch element b. Final h lives in g_h[0] (30 steps, even).
__global__ __launch_bounds__(256) void head_kernel(
    const float* __restrict__ W1, const float* __restrict__ b1,
    const float* __restrict__ W2, const float* __restrict__ b2,
    float* __restrict__ out)
{
    __shared__ float fea[2560];
    __shared__ float zp[4][64];
    __shared__ float zz[64];
    __shared__ float lg[5];

    const int b   = blockIdx.x;
    const int tid = threadIdx.x;
    const float* __restrict__ hF = g_h[0];
    const float* __restrict__ hB = g_h[0] + NSEQ * HSZ;

    // x_fea[b, slot, m] = m<128 ? hF[b*10+slot, m] : hB[b*10+slot, m]
    for (int i = tid; i < 2560; i += 256) {
        const int slot = i >> 8;
        const int m    = i & 255;
        const int n    = b * 10 + slot;
        const float v  = (m < 128) ? hF[(size_t)n * HSZ + m] : hB[(size_t)n * HSZ + m];
        fea[i] = v;
        out[2560 + (size_t)b * 2560 + i] = v;   // x_fea after y_pred (tuple order)
    }
    __syncthreads();

    // z = fea @ W1^T + b1  (64 outputs, 4-way K split)
    const int j = tid & 63;
    const int p = tid >> 6;
    float sum = 0.0f;
    const int k0 = p * 640;
    for (int k = k0; k < k0 + 640; k++) sum += fea[k] * W1[(size_t)j * 2560 + k];
    zp[p][j] = sum;
    __syncthreads();
    if (tid < 64) zz[tid] = zp[0][tid] + zp[1][tid] + zp[2][tid] + zp[3][tid] + b1[tid];
    __syncthreads();

    if (tid < 5) {
        float s = b2[tid];
        for (int k = 0; k < 64; k++) s += zz[k] * W2[tid * 64 + k];
        lg[tid] = s;
    }
    __syncthreads();
    if (tid == 0) {
        float m = lg[0];
        for (int k = 1; k < 5; k++) m = fmaxf(m, lg[k]);
        float e[5], se = 0.0f;
        for (int k = 0; k < 5; k++) { e[k] = expf(lg[k] - m); se += e[k]; }
        for (int k = 0; k < 5; k++) out[(size_t)b * 5 + k] = e[k] / se;
    }
}

extern "C" void kernel_launch(void* const* d_in, const int* in_sizes, int n_in,
                              void* d_out, int out_size) {
    const float* x     = (const float*)d_in[0];
    const float* h0    = (const float*)d_in[1];
    const float* c0    = (const float*)d_in[2];
    const float* Wih_f = (const float*)d_in[3];
    const float* Whh_f = (const float*)d_in[4];
    const float* bih_f = (const float*)d_in[5];
    const float* bhh_f = (const float*)d_in[6];
    const float* Wih_b = (const float*)d_in[7];
    const float* Whh_b = (const float*)d_in[8];
    const float* bih_b = (const float*)d_in[9];
    const float* bhh_b = (const float*)d_in[10];
    const float* W1    = (const float*)d_in[11];
    const float* b1    = (const float*)d_in[12];
    const float* W2    = (const float*)d_in[13];
    const float* b2    = (const float*)d_in[14];
    float* out = (float*)d_out;

    init_state<<<(2 * NSEQ * HSZ + 255) / 256, 256>>>(h0, c0);

    dim3 grid(HSZ / 64, NSEQ / 64, 2);   // (4, 80, 2)
    for (int s = 0; s < T_STEPS; s++) {
        lstm_step<<<grid, 256>>>(x, Wih_f, Whh_f, bih_f, bhh_f,
                                 Wih_b, Whh_b, bih_b, bhh_b, s);
    }

    head_kernel<<<NBATCH, 256>>>(W1, b1, W2, b2, out);
}